// round 4
// baseline (speedup 1.0000x reference)
#include <cuda_runtime.h>
#include <math.h>
#include <stdint.h>

#define LDIM 512
#define BDIM 64
#define CDIM 512
#define RANKS 8
#define COLS 64           // E-columns per CTA
#define GRPB 4            // batches per cluster

__device__ float g_logz[BDIM];
__device__ float g_scorep[BDIM];

// ---------------------------------------------------------------------------
__device__ __forceinline__ unsigned smem_u32(const void* p) {
    return (unsigned)__cvta_generic_to_shared(p);
}
__device__ __forceinline__ unsigned mapa_rank(unsigned saddr, unsigned rank) {
    unsigned r;
    asm("mapa.shared::cluster.u32 %0, %1, %2;" : "=r"(r) : "r"(saddr), "r"(rank));
    return r;
}
__device__ __forceinline__ void stc_f32(unsigned saddr, float v) {
    asm volatile("st.shared::cluster.f32 [%0], %1;" :: "r"(saddr), "f"(v) : "memory");
}
__device__ __forceinline__ void stc_v4(unsigned saddr, float4 v) {
    asm volatile("st.shared::cluster.v4.f32 [%0], {%1,%2,%3,%4};"
                 :: "r"(saddr), "f"(v.x), "f"(v.y), "f"(v.z), "f"(v.w) : "memory");
}
__device__ __forceinline__ void cluster_sync_() {
    asm volatile("barrier.cluster.arrive.aligned;" ::: "memory");
    asm volatile("barrier.cluster.wait.aligned;"   ::: "memory");
}
__device__ __forceinline__ unsigned long long ffma2(unsigned long long a,
                                                    unsigned long long b,
                                                    unsigned long long c) {
    unsigned long long d;
    asm("fma.rn.f32x2 %0, %1, %2, %3;" : "=l"(d) : "l"(a), "l"(b), "l"(c));
    return d;
}
__device__ __forceinline__ unsigned long long dup2(float v) {
    unsigned long long r; unsigned u = __float_as_uint(v);
    asm("mov.b64 %0, {%1, %1};" : "=l"(r) : "r"(u));
    return r;
}
__device__ __forceinline__ unsigned long long pack2(float lo, float hi) {
    unsigned long long r;
    asm("mov.b64 %0, {%1, %2};" : "=l"(r)
        : "r"(__float_as_uint(lo)), "r"(__float_as_uint(hi)));
    return r;
}
__device__ __forceinline__ float2 unpk(unsigned long long v) {
    unsigned a, b;
    asm("mov.b64 {%0, %1}, %2;" : "=r"(a), "=r"(b) : "l"(v));
    return make_float2(__uint_as_float(a), __uint_as_float(b));
}
__device__ __forceinline__ void mbar_init(unsigned addr, unsigned cnt) {
    asm volatile("mbarrier.init.shared.b64 [%0], %1;" :: "r"(addr), "r"(cnt) : "memory");
}
__device__ __forceinline__ void mbar_arrive_cluster(unsigned addr) {
    asm volatile("mbarrier.arrive.shared::cluster.b64 _, [%0];" :: "r"(addr) : "memory");
}
__device__ __forceinline__ void mbar_wait(unsigned addr, unsigned parity) {
    unsigned done;
    asm volatile(
        "{\n\t.reg .pred p;\n\t"
        "mbarrier.try_wait.parity.shared::cta.b64 p, [%1], %2;\n\t"
        "selp.b32 %0, 1, 0, p;\n\t}"
        : "=r"(done) : "r"(addr), "r"(parity) : "memory");
    if (!done) {
        asm volatile(
            "{\n\t.reg .pred P1;\n\t"
            "WL_%=:\n\t"
            "mbarrier.try_wait.parity.shared::cta.b64 P1, [%0], %1, 0x989680;\n\t"
            "@P1 bra.uni WD_%=;\n\t"
            "bra.uni WL_%=;\n\t"
            "WD_%=:\n\t}"
            :: "r"(addr), "r"(parity) : "memory");
    }
    asm volatile("fence.acq_rel.cluster;" ::: "memory");  // order peer data stores
}
__device__ __forceinline__ int mask_byte_probe(const unsigned char* m8) {
    int allnz = 1;
    for (int b = 0; b < BDIM; b++) if (m8[b] == 0) allnz = 0;
    return allnz;
}
__device__ __forceinline__ int get_mask2(const void* mask, int idx, int isbyte) {
    if (isbyte) return ((const unsigned char*)mask)[idx] != 0;
    return ((const int*)mask)[idx] != 0;
}

// ---------------------------------------------------------------------------
struct __align__(16) SM {
    float pbuf[2][CDIM][GRPB];      // 16 KB  p, double-buffered
    float part[32][GRPB][COLS];     // 32 KB  matvec partials
    float stage[COLS][GRPB];        // 1 KB   own p slice staged for push
    float pmail[2][RANKS][GRPB];    // 256 B  per-rank local maxes (lagged)
    float wred[8];
    float wsum[8];
    float fm[RANKS][GRPB], fs[RANKS][GRPB];
    unsigned char act4[LDIM][GRPB];
    unsigned char any[LDIM];
    unsigned long long barA[2], barB[2];
    int isbyte;
};

__global__ void __cluster_dims__(RANKS, 1, 1) __launch_bounds__(512, 1)
forward_kernel(const float* __restrict__ emit,
               const void*  __restrict__ mask,
               const float* __restrict__ trans,
               const float* __restrict__ tfs,
               const float* __restrict__ tte)
{
    extern __shared__ char smraw[];
    SM* sm = (SM*)smraw;

    const int t     = threadIdx.x;
    const int cta   = blockIdx.x;
    const int rank  = cta & (RANKS - 1);
    const int bbase = (cta >> 3) << 2;

    const int g    = (t >> 6) & 3;        // owner batch (t<256)
    const int col  = t & 63;              // owner local column
    const int cg_glob = rank * COLS + col;
    const int lane = t & 31;
    const int wrp  = t >> 5;

    const int cg  = t & 15;               // matvec: float4 col group
    const int seg = t >> 4;               // matvec: 16-row segment (0..31)

    // ---- barriers / probe ----
    if (t == 0) {
        mbar_init(smem_u32(&sm->barA[0]), 4);
        mbar_init(smem_u32(&sm->barA[1]), 4);
        mbar_init(smem_u32(&sm->barB[0]), 4);
        mbar_init(smem_u32(&sm->barB[1]), 4);
        sm->isbyte = mask_byte_probe((const unsigned char*)mask);
    }

    // ---- E tile -> registers (16 rows x 4 cols as 32 packed f32x2) ----
    unsigned long long Ereg[32];
    {
        const float4* tr = (const float4*)(trans) + (size_t)(rank * COLS + cg * 4) / 4;
        #pragma unroll
        for (int c = 0; c < 16; c++) {
            float4 f = tr[(size_t)(seg * 16 + c) * (CDIM / 4)];
            Ereg[2 * c]     = pack2(expf(f.x), expf(f.y));
            Ereg[2 * c + 1] = pack2(expf(f.z), expf(f.w));
        }
    }
    __syncthreads();

    // ---- mask flags ----
    const int isbyte = sm->isbyte;
    for (int i = t; i < LDIM; i += 512) {
        int anyv = 0;
        #pragma unroll
        for (int gg = 0; gg < GRPB; gg++) {
            int m = get_mask2(mask, i * BDIM + bbase + gg, isbyte);
            sm->act4[i][gg] = (unsigned char)m;
            anyv |= m;
        }
        sm->any[i] = (unsigned char)anyv;
    }

    // ---- alpha_0 + local max ----
    float a = 0.f, m_used = 0.f;
    if (t < 256) {
        a = emit[(size_t)(bbase + g) * CDIM + cg_glob] + tfs[cg_glob];
        float m = a;
        #pragma unroll
        for (int o = 16; o; o >>= 1) m = fmaxf(m, __shfl_xor_sync(0xffffffffu, m, o));
        if (lane == 0) sm->wred[wrp] = m;
    }
    __syncthreads();

    // ---- prologue exchange of alpha_0 local maxes (one cluster barrier) ----
    if (t < 32) {
        int dr = t >> 2, dg = t & 3;
        float ml = fmaxf(sm->wred[2 * dg], sm->wred[2 * dg + 1]);
        stc_f32(mapa_rank(smem_u32(&sm->fm[0][0]), dr) + (unsigned)((rank * 4 + dg) * 4), ml);
    }
    cluster_sync_();   // also publishes mbarrier inits cluster-wide
    if (t < 256) {
        float mg = sm->fm[0][g];
        #pragma unroll
        for (int r = 1; r < RANKS; r++) mg = fmaxf(mg, sm->fm[r][g]);
        m_used = mg;
        sm->stage[col][g] = __expf(a - m_used);
        // wred already holds lmax(alpha_0) parts for the first mailbox push
    }
    __syncthreads();

    // per-warp push targets
    unsigned p_dst = 0, m_dst = 0, b_dst = 0;
    if (wrp < 8) {
        p_dst = mapa_rank(smem_u32(&sm->pbuf[0][0][0]), wrp);
        m_dst = mapa_rank(smem_u32(&sm->pmail[0][0][0]), wrp);
        b_dst = mapa_rank(smem_u32(rank < 4 ? (void*)&sm->barA[0] : (void*)&sm->barB[0]), wrp);
    }
    const unsigned barA_l = smem_u32(&sm->barA[0]);
    const unsigned barB_l = smem_u32(&sm->barB[0]);
    const unsigned mybar  = (seg < 16) ? barA_l : barB_l;

    int ph[2] = {0, 0};
    int par = 0;

    for (int i = 1; i < LDIM; i++) {
        if (!sm->any[i]) continue;

        // ---- push own p slice + mailbox to rank wrp ----
        float e_reg = 0.f;
        if (t < 256) {
            // emit prefetch (consumed at combine, ~1500 cyc later)
            e_reg = emit[((size_t)i * BDIM + bbase + g) * CDIM + cg_glob];
            const float4* st4 = (const float4*)&sm->stage[0][0];
            float4 v0 = st4[lane * 2], v1 = st4[lane * 2 + 1];
            unsigned off = (unsigned)((par * CDIM + rank * COLS) * GRPB * 4);
            stc_v4(p_dst + off + (unsigned)(lane * 32),      v0);
            stc_v4(p_dst + off + (unsigned)(lane * 32 + 16), v1);
            if (lane == 0) {
                float4 mv = make_float4(fmaxf(sm->wred[0], sm->wred[1]),
                                        fmaxf(sm->wred[2], sm->wred[3]),
                                        fmaxf(sm->wred[4], sm->wred[5]),
                                        fmaxf(sm->wred[6], sm->wred[7]));
                stc_v4(m_dst + (unsigned)((par * RANKS + rank) * 16), mv);
            }
            __syncwarp();
            if (lane == 0) mbar_arrive_cluster(b_dst + (unsigned)(par * 8));
        }

        // ---- wait for my half of p ----
        mbar_wait(mybar + (unsigned)(par * 8), (unsigned)ph[par]);
        ph[par] ^= 1;

        // ---- matvec on register E ----
        {
            const float4* pv = (const float4*)&sm->pbuf[par][seg * 16][0];
            unsigned long long ac[8];
            #pragma unroll
            for (int k = 0; k < 8; k++) ac[k] = 0ull;
            #pragma unroll
            for (int c = 0; c < 16; c++) {
                float4 pq = pv[c];
                unsigned long long d0 = dup2(pq.x), d1 = dup2(pq.y),
                                   d2 = dup2(pq.z), d3 = dup2(pq.w);
                ac[0] = ffma2(d0, Ereg[2 * c], ac[0]); ac[1] = ffma2(d0, Ereg[2 * c + 1], ac[1]);
                ac[2] = ffma2(d1, Ereg[2 * c], ac[2]); ac[3] = ffma2(d1, Ereg[2 * c + 1], ac[3]);
                ac[4] = ffma2(d2, Ereg[2 * c], ac[4]); ac[5] = ffma2(d2, Ereg[2 * c + 1], ac[5]);
                ac[6] = ffma2(d3, Ereg[2 * c], ac[6]); ac[7] = ffma2(d3, Ereg[2 * c + 1], ac[7]);
            }
            #pragma unroll
            for (int gg = 0; gg < GRPB; gg++) {
                float2 lo = unpk(ac[2 * gg]), hi = unpk(ac[2 * gg + 1]);
                *(float4*)&sm->part[seg][gg][cg * 4] = make_float4(lo.x, lo.y, hi.x, hi.y);
            }
        }
        __syncthreads();

        // ---- combine: plain sum (single shared shift), update alpha ----
        if (t < 256) {
            float s = 0.f;
            #pragma unroll
            for (int r = 0; r < RANKS; r++)
                s += (sm->part[4 * r][g][col]     + sm->part[4 * r + 1][g][col])
                   + (sm->part[4 * r + 2][g][col] + sm->part[4 * r + 3][g][col]);
            float m_next = sm->pmail[par][0][g];
            #pragma unroll
            for (int r = 1; r < RANKS; r++) m_next = fmaxf(m_next, sm->pmail[par][r][g]);
            float anew = m_used + __logf(s) + e_reg;
            if (sm->act4[i][g]) a = anew;
            m_used = m_next;
            sm->stage[col][g] = __expf(a - m_next);
            float m = a;
            #pragma unroll
            for (int o = 16; o; o >>= 1) m = fmaxf(m, __shfl_xor_sync(0xffffffffu, m, o));
            if (lane == 0) sm->wred[wrp] = m;
        }
        __syncthreads();
        par ^= 1;
    }

    // ---- final: log_z = logsumexp(alpha + tte) across 8 ranks ----
    float v = -3.4e38f;
    if (t < 256) v = a + tte[cg_glob];
    {
        float m = v;
        #pragma unroll
        for (int o = 16; o; o >>= 1) m = fmaxf(m, __shfl_xor_sync(0xffffffffu, m, o));
        if (t < 256 && lane == 0) sm->wred[wrp] = m;
    }
    __syncthreads();
    if (t < 256) {
        float mloc = fmaxf(sm->wred[2 * g], sm->wred[2 * g + 1]);
        float e = expf(v - mloc);
        #pragma unroll
        for (int o = 16; o; o >>= 1) e += __shfl_xor_sync(0xffffffffu, e, o);
        if (lane == 0) sm->wsum[wrp] = e;
    }
    __syncthreads();
    if (t < 4) {
        float ml = fmaxf(sm->wred[2 * t], sm->wred[2 * t + 1]);
        float sl = sm->wsum[2 * t] + sm->wsum[2 * t + 1];
        unsigned fm0 = mapa_rank(smem_u32(&sm->fm[0][0]), 0);
        unsigned fs0 = mapa_rank(smem_u32(&sm->fs[0][0]), 0);
        stc_f32(fm0 + (unsigned)((rank * GRPB + t) * 4), ml);
        stc_f32(fs0 + (unsigned)((rank * GRPB + t) * 4), sl);
    }
    cluster_sync_();
    if (rank == 0 && t < 4) {
        float mg = sm->fm[0][t];
        #pragma unroll
        for (int r = 1; r < RANKS; r++) mg = fmaxf(mg, sm->fm[r][t]);
        float tot = 0.f;
        #pragma unroll
        for (int r = 0; r < RANKS; r++) tot += sm->fs[r][t] * expf(sm->fm[r][t] - mg);
        g_logz[bbase + t] = mg + logf(tot);
    }
}

// ---------------------------------------------------------------------------
__global__ __launch_bounds__(512) void score_kernel(
    const float* __restrict__ emit,
    const int*   __restrict__ target,
    const void*  __restrict__ mask,
    const float* __restrict__ trans,
    const float* __restrict__ tfs,
    const float* __restrict__ tte)
{
    __shared__ int s_isbyte;
    __shared__ float red[16];
    const int t = threadIdx.x, warp = t >> 5, lane = t & 31;
    if (t == 0) s_isbyte = mask_byte_probe((const unsigned char*)mask);
    __syncthreads();
    const int isbyte = s_isbyte;

    const int idx = blockIdx.x * 512 + t;
    const int i = idx >> 6;
    const int b = idx & 63;

    float contrib = 0.f;
    if (get_mask2(mask, i * BDIM + b, isbyte)) {
        int ti = target[i * BDIM + b];
        contrib = emit[((size_t)i * BDIM + b) * CDIM + ti];
        if (i > 0) {
            int tp = target[(i - 1) * BDIM + b];
            contrib += trans[(size_t)tp * CDIM + ti];
        } else {
            contrib += tfs[ti];
        }
        int nxt = (i + 1 < LDIM) ? get_mask2(mask, (i + 1) * BDIM + b, isbyte) : 0;
        if (!nxt) contrib += tte[ti];
    }
    #pragma unroll
    for (int o = 16; o; o >>= 1) contrib += __shfl_xor_sync(0xffffffffu, contrib, o);
    if (lane == 0) red[warp] = contrib;
    __syncthreads();
    if (t == 0) {
        float s = 0.f;
        #pragma unroll
        for (int w = 0; w < 16; w++) s += red[w];
        g_scorep[blockIdx.x] = s;
    }
}

// ---------------------------------------------------------------------------
__global__ void finalize_kernel(float* __restrict__ out) {
    __shared__ float red[2];
    const int t = threadIdx.x, lane = t & 31, warp = t >> 5;
    float v = (t < BDIM) ? (g_logz[t] - g_scorep[t]) : 0.f;
    #pragma unroll
    for (int o = 16; o; o >>= 1) v += __shfl_xor_sync(0xffffffffu, v, o);
    if (lane == 0) red[warp] = v;
    __syncthreads();
    if (t == 0) out[0] = (red[0] + red[1]) / (float)BDIM;
}

// ---------------------------------------------------------------------------
extern "C" void kernel_launch(void* const* d_in, const int* in_sizes, int n_in,
                              void* d_out, int out_size) {
    const float* emit   = (const float*)d_in[0];
    const int*   target = (const int*)  d_in[1];
    const void*  mask   =               d_in[2];
    const float* trans  = (const float*)d_in[3];
    const float* tfs    = (const float*)d_in[4];
    const float* tte    = (const float*)d_in[5];
    float* out = (float*)d_out;

    cudaFuncSetAttribute(forward_kernel,
                         cudaFuncAttributeMaxDynamicSharedMemorySize, (int)sizeof(SM));

    forward_kernel<<<16 * RANKS, 512, sizeof(SM)>>>(emit, mask, trans, tfs, tte);
    score_kernel<<<64, 512>>>(emit, target, mask, trans, tfs, tte);
    finalize_kernel<<<1, 64>>>(out);
}

// round 5
// speedup vs baseline: 1.2095x; 1.2095x over previous
#include <cuda_runtime.h>
#include <math.h>
#include <stdint.h>

#define LDIM 512
#define BDIM 64
#define CDIM 512
#define RANKS 8
#define COLS 64           // E-columns per CTA
#define GRPB 4            // batches per cluster

__device__ float g_logz[BDIM];
__device__ float g_scorep[BDIM];

// ---------------------------------------------------------------------------
__device__ __forceinline__ unsigned smem_u32(const void* p) {
    return (unsigned)__cvta_generic_to_shared(p);
}
__device__ __forceinline__ unsigned mapa_rank(unsigned saddr, unsigned rank) {
    unsigned r;
    asm("mapa.shared::cluster.u32 %0, %1, %2;" : "=r"(r) : "r"(saddr), "r"(rank));
    return r;
}
__device__ __forceinline__ void stc_f32(unsigned saddr, float v) {
    asm volatile("st.shared::cluster.f32 [%0], %1;" :: "r"(saddr), "f"(v) : "memory");
}
__device__ __forceinline__ void stc_v4(unsigned saddr, float4 v) {
    asm volatile("st.shared::cluster.v4.f32 [%0], {%1,%2,%3,%4};"
                 :: "r"(saddr), "f"(v.x), "f"(v.y), "f"(v.z), "f"(v.w) : "memory");
}
__device__ __forceinline__ void cluster_sync_() {
    asm volatile("barrier.cluster.arrive.aligned;" ::: "memory");
    asm volatile("barrier.cluster.wait.aligned;"   ::: "memory");
}
__device__ __forceinline__ unsigned long long ffma2(unsigned long long a,
                                                    unsigned long long b,
                                                    unsigned long long c) {
    unsigned long long d;
    asm("fma.rn.f32x2 %0, %1, %2, %3;" : "=l"(d) : "l"(a), "l"(b), "l"(c));
    return d;
}
__device__ __forceinline__ unsigned long long dup2(float v) {
    unsigned long long r; unsigned u = __float_as_uint(v);
    asm("mov.b64 %0, {%1, %1};" : "=l"(r) : "r"(u));
    return r;
}
__device__ __forceinline__ float2 unpk(unsigned long long v) {
    unsigned a, b;
    asm("mov.b64 {%0, %1}, %2;" : "=r"(a), "=r"(b) : "l"(v));
    return make_float2(__uint_as_float(a), __uint_as_float(b));
}
__device__ __forceinline__ int mask_byte_probe(const unsigned char* m8) {
    int allnz = 1;
    for (int b = 0; b < BDIM; b++) if (m8[b] == 0) allnz = 0;
    return allnz;
}
__device__ __forceinline__ int get_mask2(const void* mask, int idx, int isbyte) {
    if (isbyte) return ((const unsigned char*)mask)[idx] != 0;
    return ((const int*)mask)[idx] != 0;
}

// ---------------------------------------------------------------------------
struct __align__(16) SM {
    float E[CDIM * COLS];           // 128 KB  exp(trans) local-col slice
    float pbuf[2][CDIM][GRPB];      // 16 KB   assembled p, double-buffered
    float part[32][GRPB][COLS];     // 32 KB   matvec partials
    float stage[COLS][GRPB];        // 1 KB    own p slice staged for push
    float pmail[2][RANKS][GRPB];    // 256 B   per-rank local maxes (lagged)
    float wred[8];
    float wsum[8];
    float fm[RANKS][GRPB], fs[RANKS][GRPB];
    unsigned char act4[LDIM][GRPB];
    unsigned char any[LDIM];
    int isbyte;
};

__global__ void __cluster_dims__(RANKS, 1, 1) __launch_bounds__(512, 1)
forward_kernel(const float* __restrict__ emit,
               const void*  __restrict__ mask,
               const float* __restrict__ trans,
               const float* __restrict__ tfs,
               const float* __restrict__ tte)
{
    extern __shared__ char smraw[];
    SM* sm = (SM*)smraw;

    const int t     = threadIdx.x;
    const int cta   = blockIdx.x;
    const int rank  = cta & (RANKS - 1);
    const int bbase = (cta >> 3) << 2;

    const int g    = (t >> 6) & 3;        // owner batch (t<256)
    const int col  = t & 63;              // owner local column
    const int cg_glob = rank * COLS + col;
    const int lane = t & 31;
    const int wrp  = t >> 5;

    const int cg  = t & 15;               // matvec: float4 col group
    const int seg = t >> 4;               // matvec: 16-row segment (0..31)

    if (t == 0) sm->isbyte = mask_byte_probe((const unsigned char*)mask);

    // ---- E slice = exp(trans[:, rank*64 .. rank*64+64]) ----
    for (int idx = t; idx < CDIM * COLS; idx += 512) {
        int row = idx >> 6, c = idx & 63;
        sm->E[idx] = expf(trans[(size_t)row * CDIM + rank * COLS + c]);
    }
    __syncthreads();

    // ---- mask flags ----
    const int isbyte = sm->isbyte;
    for (int i = t; i < LDIM; i += 512) {
        int anyv = 0;
        #pragma unroll
        for (int gg = 0; gg < GRPB; gg++) {
            int m = get_mask2(mask, i * BDIM + bbase + gg, isbyte);
            sm->act4[i][gg] = (unsigned char)m;
            anyv |= m;
        }
        sm->any[i] = (unsigned char)anyv;
    }

    // ---- alpha_0 + local max ----
    float a = 0.f, m_used = 0.f;
    if (t < 256) {
        a = emit[(size_t)(bbase + g) * CDIM + cg_glob] + tfs[cg_glob];
        float m = a;
        #pragma unroll
        for (int o = 16; o; o >>= 1) m = fmaxf(m, __shfl_xor_sync(0xffffffffu, m, o));
        if (lane == 0) sm->wred[wrp] = m;
    }
    __syncthreads();

    // ---- prologue: exchange alpha_0 local maxes -> m_used, first stage ----
    if (t < 32) {
        int dr = t >> 2, dg = t & 3;
        float ml = fmaxf(sm->wred[2 * dg], sm->wred[2 * dg + 1]);
        stc_f32(mapa_rank(smem_u32(&sm->fm[0][0]), dr) + (unsigned)((rank * 4 + dg) * 4), ml);
    }
    cluster_sync_();
    if (t < 256) {
        float mg = sm->fm[0][g];
        #pragma unroll
        for (int r = 1; r < RANKS; r++) mg = fmaxf(mg, sm->fm[r][g]);
        m_used = mg;
        sm->stage[col][g] = __expf(a - m_used);
    }
    __syncthreads();

    // per-warp push targets (warp wrp ships to rank wrp)
    unsigned p_dst = 0, m_dst = 0;
    if (wrp < 8) {
        p_dst = mapa_rank(smem_u32(&sm->pbuf[0][0][0]), wrp);
        m_dst = mapa_rank(smem_u32(&sm->pmail[0][0][0]), wrp);
    }

    int par = 0;
    for (int i = 1; i < LDIM; i++) {
        if (!sm->any[i]) continue;

        // ---- push: warp wrp ships full stage slice + mailbox to rank wrp ----
        float e_reg = 0.f;
        if (t < 256) {
            e_reg = emit[((size_t)i * BDIM + bbase + g) * CDIM + cg_glob];  // prefetch
            const float4* st4 = (const float4*)&sm->stage[0][0];
            float4 v0 = st4[lane * 2], v1 = st4[lane * 2 + 1];
            unsigned off = (unsigned)((par * CDIM + rank * COLS) * GRPB * 4);
            stc_v4(p_dst + off + (unsigned)(lane * 32),      v0);
            stc_v4(p_dst + off + (unsigned)(lane * 32 + 16), v1);
            if (lane == 0) {
                float4 mv = make_float4(fmaxf(sm->wred[0], sm->wred[1]),
                                        fmaxf(sm->wred[2], sm->wred[3]),
                                        fmaxf(sm->wred[4], sm->wred[5]),
                                        fmaxf(sm->wred[6], sm->wred[7]));
                stc_v4(m_dst + (unsigned)((par * RANKS + rank) * 16), mv);
            }
        }
        cluster_sync_();   // all pushes visible everywhere

        // ---- matvec on SMEM E slice (4 batches per E element) ----
        {
            const ulonglong2* Ev = (const ulonglong2*)sm->E + (size_t)seg * 16 * (COLS / 4) + cg;
            const float4*     pv = (const float4*)&sm->pbuf[par][seg * 16][0];
            unsigned long long ac[8];
            #pragma unroll
            for (int k = 0; k < 8; k++) ac[k] = 0ull;
            #pragma unroll
            for (int c = 0; c < 16; c++) {
                ulonglong2 e  = Ev[(size_t)c * (COLS / 4)];
                float4     pq = pv[c];
                unsigned long long d0 = dup2(pq.x), d1 = dup2(pq.y),
                                   d2 = dup2(pq.z), d3 = dup2(pq.w);
                ac[0] = ffma2(d0, e.x, ac[0]); ac[1] = ffma2(d0, e.y, ac[1]);
                ac[2] = ffma2(d1, e.x, ac[2]); ac[3] = ffma2(d1, e.y, ac[3]);
                ac[4] = ffma2(d2, e.x, ac[4]); ac[5] = ffma2(d2, e.y, ac[5]);
                ac[6] = ffma2(d3, e.x, ac[6]); ac[7] = ffma2(d3, e.y, ac[7]);
            }
            #pragma unroll
            for (int gg = 0; gg < GRPB; gg++) {
                float2 lo = unpk(ac[2 * gg]), hi = unpk(ac[2 * gg + 1]);
                *(float4*)&sm->part[seg][gg][cg * 4] = make_float4(lo.x, lo.y, hi.x, hi.y);
            }
        }
        __syncthreads();

        // ---- combine: plain sum (single shared shift), update alpha,
        //      compute next stage + warp maxes (lagged-max pipeline) ----
        if (t < 256) {
            float s = 0.f;
            #pragma unroll
            for (int r = 0; r < RANKS; r++)
                s += (sm->part[4 * r][g][col]     + sm->part[4 * r + 1][g][col])
                   + (sm->part[4 * r + 2][g][col] + sm->part[4 * r + 3][g][col]);
            float m_next = sm->pmail[par][0][g];
            #pragma unroll
            for (int r = 1; r < RANKS; r++) m_next = fmaxf(m_next, sm->pmail[par][r][g]);
            float anew = m_used + __logf(s) + e_reg;
            if (sm->act4[i][g]) a = anew;
            m_used = m_next;
            sm->stage[col][g] = __expf(a - m_next);
            float m = a;
            #pragma unroll
            for (int o = 16; o; o >>= 1) m = fmaxf(m, __shfl_xor_sync(0xffffffffu, m, o));
            if (lane == 0) sm->wred[wrp] = m;
        }
        __syncthreads();
        par ^= 1;
    }

    // ---- final: log_z = logsumexp(alpha + tte) across 8 ranks ----
    float v = -3.4e38f;
    if (t < 256) v = a + tte[cg_glob];
    {
        float m = v;
        #pragma unroll
        for (int o = 16; o; o >>= 1) m = fmaxf(m, __shfl_xor_sync(0xffffffffu, m, o));
        if (t < 256 && lane == 0) sm->wred[wrp] = m;
    }
    __syncthreads();
    if (t < 256) {
        float mloc = fmaxf(sm->wred[2 * g], sm->wred[2 * g + 1]);
        float e = expf(v - mloc);
        #pragma unroll
        for (int o = 16; o; o >>= 1) e += __shfl_xor_sync(0xffffffffu, e, o);
        if (lane == 0) sm->wsum[wrp] = e;
    }
    __syncthreads();
    if (t < 4) {
        float ml = fmaxf(sm->wred[2 * t], sm->wred[2 * t + 1]);
        float sl = sm->wsum[2 * t] + sm->wsum[2 * t + 1];
        unsigned fm0 = mapa_rank(smem_u32(&sm->fm[0][0]), 0);
        unsigned fs0 = mapa_rank(smem_u32(&sm->fs[0][0]), 0);
        stc_f32(fm0 + (unsigned)((rank * GRPB + t) * 4), ml);
        stc_f32(fs0 + (unsigned)((rank * GRPB + t) * 4), sl);
    }
    cluster_sync_();
    if (rank == 0 && t < 4) {
        float mg = sm->fm[0][t];
        #pragma unroll
        for (int r = 1; r < RANKS; r++) mg = fmaxf(mg, sm->fm[r][t]);
        float tot = 0.f;
        #pragma unroll
        for (int r = 0; r < RANKS; r++) tot += sm->fs[r][t] * expf(sm->fm[r][t] - mg);
        g_logz[bbase + t] = mg + logf(tot);
    }
}

// ---------------------------------------------------------------------------
__global__ __launch_bounds__(512) void score_kernel(
    const float* __restrict__ emit,
    const int*   __restrict__ target,
    const void*  __restrict__ mask,
    const float* __restrict__ trans,
    const float* __restrict__ tfs,
    const float* __restrict__ tte)
{
    __shared__ int s_isbyte;
    __shared__ float red[16];
    const int t = threadIdx.x, warp = t >> 5, lane = t & 31;
    if (t == 0) s_isbyte = mask_byte_probe((const unsigned char*)mask);
    __syncthreads();
    const int isbyte = s_isbyte;

    const int idx = blockIdx.x * 512 + t;
    const int i = idx >> 6;
    const int b = idx & 63;

    float contrib = 0.f;
    if (get_mask2(mask, i * BDIM + b, isbyte)) {
        int ti = target[i * BDIM + b];
        contrib = emit[((size_t)i * BDIM + b) * CDIM + ti];
        if (i > 0) {
            int tp = target[(i - 1) * BDIM + b];
            contrib += trans[(size_t)tp * CDIM + ti];
        } else {
            contrib += tfs[ti];
        }
        int nxt = (i + 1 < LDIM) ? get_mask2(mask, (i + 1) * BDIM + b, isbyte) : 0;
        if (!nxt) contrib += tte[ti];
    }
    #pragma unroll
    for (int o = 16; o; o >>= 1) contrib += __shfl_xor_sync(0xffffffffu, contrib, o);
    if (lane == 0) red[warp] = contrib;
    __syncthreads();
    if (t == 0) {
        float s = 0.f;
        #pragma unroll
        for (int w = 0; w < 16; w++) s += red[w];
        g_scorep[blockIdx.x] = s;
    }
}

// ---------------------------------------------------------------------------
__global__ void finalize_kernel(float* __restrict__ out) {
    __shared__ float red[2];
    const int t = threadIdx.x, lane = t & 31, warp = t >> 5;
    float v = (t < BDIM) ? (g_logz[t] - g_scorep[t]) : 0.f;
    #pragma unroll
    for (int o = 16; o; o >>= 1) v += __shfl_xor_sync(0xffffffffu, v, o);
    if (lane == 0) red[warp] = v;
    __syncthreads();
    if (t == 0) out[0] = (red[0] + red[1]) / (float)BDIM;
}

// ---------------------------------------------------------------------------
extern "C" void kernel_launch(void* const* d_in, const int* in_sizes, int n_in,
                              void* d_out, int out_size) {
    const float* emit   = (const float*)d_in[0];
    const int*   target = (const int*)  d_in[1];
    const void*  mask   =               d_in[2];
    const float* trans  = (const float*)d_in[3];
    const float* tfs    = (const float*)d_in[4];
    const float* tte    = (const float*)d_in[5];
    float* out = (float*)d_out;

    cudaFuncSetAttribute(forward_kernel,
                         cudaFuncAttributeMaxDynamicSharedMemorySize, (int)sizeof(SM));

    forward_kernel<<<16 * RANKS, 512, sizeof(SM)>>>(emit, mask, trans, tfs, tte);
    score_kernel<<<64, 512>>>(emit, target, mask, trans, tfs, tte);
    finalize_kernel<<<1, 64>>>(out);
}